// round 11
// baseline (speedup 1.0000x reference)
#include <cuda_runtime.h>

#define T_TOK   32768
#define D_DIM   2048
#define NE      8
#define NGROUPS (T_TOK / 16)   // 2048 groups of 16 tokens
#define NITER   (D_DIM / 32)   // 64 inner iterations
#define THREADS 448
#define NWARPS  14
#define SMEM_W  131072         // weights region
#define HBUF_SZ 2048           // one h stage buffer (16 tokens x 128B)

// ---- Blackwell packed f32x2 helpers ----
__device__ __forceinline__ unsigned long long dup2(float x) {
    unsigned long long r;
    asm("mov.b64 %0, {%1, %1};" : "=l"(r) : "f"(x));
    return r;
}
__device__ __forceinline__ void fma2(unsigned long long& a, unsigned long long b, unsigned long long c) {
    asm("fma.rn.f32x2 %0, %1, %2, %0;" : "+l"(a) : "l"(b), "l"(c));
}
__device__ __forceinline__ unsigned long long add2(unsigned long long a, unsigned long long b) {
    unsigned long long r;
    asm("add.rn.f32x2 %0, %1, %2;" : "=l"(r) : "l"(a), "l"(b));
    return r;
}
__device__ __forceinline__ void unpack2(unsigned long long v, float& lo, float& hi) {
    asm("mov.b64 {%0, %1}, %2;" : "=f"(lo), "=f"(hi) : "l"(v));
}
__device__ __forceinline__ void cp16(unsigned smem_dst, const void* gsrc) {
    asm volatile("cp.async.cg.shared.global [%0], [%1], 16;" :: "r"(smem_dst), "l"(gsrc));
}
__device__ __forceinline__ void cp_commit() {
    asm volatile("cp.async.commit_group;" ::: "memory");
}
__device__ __forceinline__ void cp_wait1() {
    asm volatile("cp.async.wait_group 1;" ::: "memory");
}

// Persistent kernel: grid=#SMs, 1 CTA/SM, 448 threads (14 warps).
// smem: [0,128K) XOR-swizzled weights ([k][Ww e0..7|Wn e0..7], ^((k>>2)&7)<<4);
//       [128K,212K) per-warp h stage buffers (3 x 2KB, cp.async.cg).
// Lane = (trow = lane>>4: token octet 0..1, esplit = (lane>>3)&1: W/N half,
//         sub = lane&7: k-slice). Warp group = 16 tokens, T=8 tokens/lane,
// acc = 8 tok x 8 vals (W-half or N-half) = 64 regs -> 14 warps fit the RF.
extern "C" __global__ void __launch_bounds__(THREADS, 1)
router_kernel(const float* __restrict__ h,  const float* __restrict__ Ww,
              const float* __restrict__ bw, const float* __restrict__ Wn,
              const float* __restrict__ bn, const float* __restrict__ eps,
              float* __restrict__ out)
{
    extern __shared__ char smem_all[];
    char* swb = smem_all;                       // weights

    const int tid = threadIdx.x;

    // Fill weights into smem with swizzle.
    for (int idx = tid; idx < D_DIM * NE; idx += THREADS) {
        int k = idx >> 3, e = idx & 7;
        unsigned sx = ((unsigned)(k >> 2) & 7u) << 4;
        unsigned offW = ((unsigned)k * 64u + (unsigned)e * 4u) ^ sx;
        unsigned offN = ((unsigned)k * 64u + 32u + (unsigned)e * 4u) ^ sx;
        *(float*)(swb + offW) = Ww[idx];
        *(float*)(swb + offN) = Wn[idx];
    }
    __syncthreads();

    const int warp   = tid >> 5;
    const int lane   = tid & 31;
    const int sub    = lane & 7;           // k-slice 0..7
    const int esplit = (lane >> 3) & 1;    // 0 = W half, 1 = N half
    const int trow   = lane >> 4;          // token octet 0..1
    const unsigned sx = (unsigned)sub << 4;

    const unsigned smem_base_u32 = (unsigned)__cvta_generic_to_shared(smem_all);
    const unsigned hbuf0 = smem_base_u32 + SMEM_W + (unsigned)warp * (3 * HBUF_SZ);
    char* hbuf0p = smem_all + SMEM_W + warp * (3 * HBUF_SZ);

    for (int g = warp * gridDim.x + blockIdx.x; g < NGROUPS; g += gridDim.x * NWARPS) {
        // Staging role: lane copies chunk (lane&7) of tokens (lane>>3) + q*4.
        const int tok_st = lane >> 3;           // 0..3
        const char* gst = (const char*)h
                        + ((size_t)(g * 16 + tok_st)) * (D_DIM * 4) + (lane & 7) * 16;
        const unsigned dst_lane_off = (unsigned)(tok_st * 128 + (lane & 7) * 16);

        unsigned long long acc[8][4];
        #pragma unroll
        for (int r = 0; r < 8; ++r)
            #pragma unroll
            for (int p = 0; p < 4; ++p) acc[r][p] = 0ull;

        // Warmup: stage iters 0,1 into slots 0,1.
        #pragma unroll
        for (int st = 0; st < 2; ++st) {
            const unsigned dst = hbuf0 + st * HBUF_SZ + dst_lane_off;
            #pragma unroll
            for (int q = 0; q < 4; ++q)
                cp16(dst + q * 512, gst + (size_t)q * 4 * (D_DIM * 4) + st * 128);
            cp_commit();
        }

        int rs = 0;        // read slot  (i % 3)
        int ws = 2;        // write slot ((i+2) % 3)
        #pragma unroll 2
        for (int i = 0; i < NITER; ++i) {
            cp_wait1();                        // stage i complete

            // Read this iter's h: 8 tokens (trow octet) x 4 floats (chunk sub).
            const char* rb = hbuf0p + rs * HBUF_SZ;
            float4 cc4[8];
            #pragma unroll
            for (int r = 0; r < 8; ++r)
                cc4[r] = *(const float4*)(rb + (unsigned)((trow * 8 + r) * 128 + sub * 16));

            // Stage iter i+2 into slot ws.
            if (i + 2 < NITER) {
                const unsigned dst = hbuf0 + ws * HBUF_SZ + dst_lane_off;
                const char* gsi = gst + (size_t)(i + 2) * 128;
                #pragma unroll
                for (int q = 0; q < 4; ++q)
                    cp16(dst + q * 512, gsi + (size_t)q * 4 * (D_DIM * 4));
            }
            cp_commit();

            const float cc[8][4] = {
                {cc4[0].x, cc4[0].y, cc4[0].z, cc4[0].w},
                {cc4[1].x, cc4[1].y, cc4[1].z, cc4[1].w},
                {cc4[2].x, cc4[2].y, cc4[2].z, cc4[2].w},
                {cc4[3].x, cc4[3].y, cc4[3].z, cc4[3].w},
                {cc4[4].x, cc4[4].y, cc4[4].z, cc4[4].w},
                {cc4[5].x, cc4[5].y, cc4[5].z, cc4[5].w},
                {cc4[6].x, cc4[6].y, cc4[6].z, cc4[6].w},
                {cc4[7].x, cc4[7].y, cc4[7].z, cc4[7].w}
            };

            const int kbase = i * 32 + sub * 4;
            #pragma unroll
            for (int j = 0; j < 4; ++j) {
                const unsigned A = (unsigned)(kbase + j) * 64u + (unsigned)esplit * 32u;
                ulonglong2 v01 = *(const ulonglong2*)(swb + ((A      ) ^ sx));
                ulonglong2 v23 = *(const ulonglong2*)(swb + ((A + 16u) ^ sx));
                #pragma unroll
                for (int r = 0; r < 8; ++r) {
                    unsigned long long hh = dup2(cc[r][j]);
                    fma2(acc[r][0], v01.x, hh); fma2(acc[r][1], v01.y, hh);
                    fma2(acc[r][2], v23.x, hh); fma2(acc[r][3], v23.y, hh);
                }
            }

            rs = (rs == 2) ? 0 : rs + 1;
            ws = (ws == 2) ? 0 : ws + 1;
        }

        // Butterfly all-reduce across the 8 sub lanes (xor 1, 2, 4).
        #pragma unroll
        for (int s = 1; s <= 4; s <<= 1) {
            #pragma unroll
            for (int r = 0; r < 8; ++r)
                #pragma unroll
                for (int p = 0; p < 4; ++p) {
                    unsigned long long o = __shfl_xor_sync(0xffffffffu, acc[r][p], s);
                    acc[r][p] = add2(acc[r][p], o);
                }
        }

        // Each lane keeps token r = sub; swap halves with the xor-8 partner.
        unsigned long long sel[4], oth[4];
        #pragma unroll
        for (int r = 0; r < 8; ++r)
            if (sub == r) {
                #pragma unroll
                for (int p = 0; p < 4; ++p) sel[p] = acc[r][p];
            }
        #pragma unroll
        for (int p = 0; p < 4; ++p)
            oth[p] = __shfl_xor_sync(0xffffffffu, sel[p], 8);

        // esplit==0 lanes (16 per warp) finish token g*16 + trow*8 + sub:
        // sel = W-half (logits), oth = N-half (noise pre-activation).
        if (esplit == 0) {
            const int tok = g * 16 + trow * 8 + sub;

            float lg[8], nr[8];
            unpack2(sel[0], lg[0], lg[1]); unpack2(sel[1], lg[2], lg[3]);
            unpack2(sel[2], lg[4], lg[5]); unpack2(sel[3], lg[6], lg[7]);
            unpack2(oth[0], nr[0], nr[1]); unpack2(oth[1], nr[2], nr[3]);
            unpack2(oth[2], nr[4], nr[5]); unpack2(oth[3], nr[6], nr[7]);

            float4 e0 = __ldg((const float4*)(eps + (size_t)tok * 8));
            float4 e1 = __ldg((const float4*)(eps + (size_t)tok * 8) + 1);
            float ee[8] = {e0.x, e0.y, e0.z, e0.w, e1.x, e1.y, e1.z, e1.w};

            float noisy[8];
            #pragma unroll
            for (int e = 0; e < 8; ++e) {
                float x  = nr[e] + bn[e];
                float sp = (x > 0.f) ? (x + log1pf(expf(-x))) : log1pf(expf(x));
                noisy[e] = lg[e] + bw[e] + ee[e] * sp;
            }

            // Full softmax (max-subtracted, matches jax.nn.softmax)
            float m = noisy[0];
            #pragma unroll
            for (int e = 1; e < 8; ++e) m = fmaxf(m, noisy[e]);
            float ex[8], ssum = 0.f;
            #pragma unroll
            for (int e = 0; e < 8; ++e) { ex[e] = expf(noisy[e] - m); ssum += ex[e]; }
            float inv = 1.f / ssum;

            // Top-2, first-occurrence tie-break (matches jax.lax.top_k)
            int i1 = 0; float v1 = noisy[0];
            #pragma unroll
            for (int e = 1; e < 8; ++e) if (noisy[e] > v1) { v1 = noisy[e]; i1 = e; }
            int i2 = -1; float v2 = -3.4e38f;
            #pragma unroll
            for (int e = 0; e < 8; ++e) if (e != i1 && noisy[e] > v2) { v2 = noisy[e]; i2 = e; }

            // Sparse softmax over exactly the two kept entries (others exactly 0)
            float edd = expf(v2 - v1);
            float s1  = 1.f / (1.f + edd);
            float s2  = edd * s1;

            float sp8[8];
            #pragma unroll
            for (int e = 0; e < 8; ++e)
                sp8[e] = (e == i1) ? s1 : ((e == i2) ? s2 : 0.f);

            float* outS = out + (size_t)tok * 8;
            float* outI = out + (size_t)T_TOK * 8  + (size_t)tok * 2;
            float* outF = out + (size_t)T_TOK * 10 + (size_t)tok * 8;

            ((float4*)outS)[0] = make_float4(sp8[0], sp8[1], sp8[2], sp8[3]);
            ((float4*)outS)[1] = make_float4(sp8[4], sp8[5], sp8[6], sp8[7]);
            ((float2*)outI)[0] = make_float2((float)i1, (float)i2);
            ((float4*)outF)[0] = make_float4(ex[0] * inv, ex[1] * inv, ex[2] * inv, ex[3] * inv);
            ((float4*)outF)[1] = make_float4(ex[4] * inv, ex[5] * inv, ex[6] * inv, ex[7] * inv);
        }
    }
}

extern "C" void kernel_launch(void* const* d_in, const int* in_sizes, int n_in,
                              void* d_out, int out_size)
{
    const float* h   = (const float*)d_in[0];
    const float* Ww  = (const float*)d_in[1];
    const float* bw  = (const float*)d_in[2];
    const float* Wn  = (const float*)d_in[3];
    const float* bn  = (const float*)d_in[4];
    const float* eps = (const float*)d_in[5];

    const int smem = SMEM_W + NWARPS * 3 * HBUF_SZ;   // 131072 + 86016 = 217088
    cudaFuncSetAttribute(router_kernel, cudaFuncAttributeMaxDynamicSharedMemorySize, smem);

    int nsm = 148;
    cudaDeviceGetAttribute(&nsm, cudaDevAttrMultiProcessorCount, 0);

    router_kernel<<<nsm, THREADS, smem>>>(h, Ww, bw, Wn, bn, eps, (float*)d_out);
}

// round 12
// speedup vs baseline: 1.0641x; 1.0641x over previous
#include <cuda_runtime.h>

#define T_TOK   32768
#define D_DIM   2048
#define NE      8
#define NGROUPS (T_TOK / 32)   // 1024 groups of 32 tokens
#define NITER   (D_DIM / 32)   // 64 inner iterations
#define NCTA    128            // 128 CTAs x 8 warps = 1024 slots = NGROUPS exactly
#define SMEM_W  131072         // weights region
#define HBUF_SZ 4096           // one h stage buffer (32 tokens x 128B)

// ---- Blackwell packed f32x2 helpers ----
__device__ __forceinline__ unsigned long long dup2(float x) {
    unsigned long long r;
    asm("mov.b64 %0, {%1, %1};" : "=l"(r) : "f"(x));
    return r;
}
__device__ __forceinline__ void fma2(unsigned long long& a, unsigned long long b, unsigned long long c) {
    asm("fma.rn.f32x2 %0, %1, %2, %0;" : "+l"(a) : "l"(b), "l"(c));
}
__device__ __forceinline__ unsigned long long add2(unsigned long long a, unsigned long long b) {
    unsigned long long r;
    asm("add.rn.f32x2 %0, %1, %2;" : "=l"(r) : "l"(a), "l"(b));
    return r;
}
__device__ __forceinline__ void unpack2(unsigned long long v, float& lo, float& hi) {
    asm("mov.b64 {%0, %1}, %2;" : "=f"(lo), "=f"(hi) : "l"(v));
}
__device__ __forceinline__ void pf_l2(const void* p) {
    asm volatile("prefetch.global.L2 [%0];" :: "l"(p));
}
__device__ __forceinline__ void cp16(unsigned smem_dst, const void* gsrc) {
    asm volatile("cp.async.cg.shared.global [%0], [%1], 16;" :: "r"(smem_dst), "l"(gsrc));
}
__device__ __forceinline__ void cp_commit() {
    asm volatile("cp.async.commit_group;" ::: "memory");
}
__device__ __forceinline__ void cp_wait1() {
    asm volatile("cp.async.wait_group 1;" ::: "memory");
}

// Persistent kernel: grid=128 CTAs (8 warps each -> 1024 warp slots, exactly
// one 32-token group per warp, 8 active warps on EVERY SM = 2.0/SMSP).
// smem: [0,128K) XOR-swizzled weights ([k][Ww e0..7|Wn e0..7], ^((k>>2)&7)<<4);
//       [128K,224K) per-warp h stage buffers (3 x 4KB each, cp.async.cg).
// Lane = (trow = lane>>3: token octet 0..3, sub = lane&7: k-slice).
// Each lane accumulates 8 tokens; h flows gmem->L2->smem (no L1, no registers,
// no scoreboard stall) with stage-ahead 2 + L2 prefetch at distance 6.
extern "C" __global__ void __launch_bounds__(256, 1)
router_kernel(const float* __restrict__ h,  const float* __restrict__ Ww,
              const float* __restrict__ bw, const float* __restrict__ Wn,
              const float* __restrict__ bn, const float* __restrict__ eps,
              float* __restrict__ out)
{
    extern __shared__ char smem_all[];
    char* swb = smem_all;                       // weights

    const int tid = threadIdx.x;

    // Fill weights into smem with swizzle.
    #pragma unroll
    for (int it = 0; it < (D_DIM * NE) / 256; ++it) {
        int idx = tid + it * 256;          // 0..16383
        int k = idx >> 3, e = idx & 7;
        unsigned sx = ((unsigned)(k >> 2) & 7u) << 4;
        unsigned offW = ((unsigned)k * 64u + (unsigned)e * 4u) ^ sx;
        unsigned offN = ((unsigned)k * 64u + 32u + (unsigned)e * 4u) ^ sx;
        *(float*)(swb + offW) = Ww[idx];
        *(float*)(swb + offN) = Wn[idx];
    }
    __syncthreads();

    const int warp = tid >> 5;
    const int lane = tid & 31;
    const int trow = lane >> 3;          // token octet 0..3
    const int sub  = lane & 7;           // k-slice 0..7
    const unsigned subx = (unsigned)sub << 4;   // weight swizzle term

    // This warp's 3 h stage buffers (shared-space u32 addresses).
    const unsigned smem_base_u32 =
        (unsigned)__cvta_generic_to_shared(smem_all);
    const unsigned hbuf0 = smem_base_u32 + SMEM_W + (unsigned)warp * (3 * HBUF_SZ);
    char* hbuf0p = smem_all + SMEM_W + warp * (3 * HBUF_SZ);

    for (int g = warp * gridDim.x + blockIdx.x; g < NGROUPS; g += gridDim.x * 8) {
        // Staging lane role: instr q copies chunk sub (16B) of token q*4+trow.
        const char* gst = (const char*)h
                        + ((size_t)(g * 32 + trow)) * (D_DIM * 4) + sub * 16;
        // Read role: lane reads chunk sub of tokens trow*8 + r.
        const unsigned rdbase = (unsigned)(trow * 1024 + sub * 16);

        // Per-lane L2 prefetch stream (R7 form: 8 dedup-friendly instrs/iter
        // issued across the r-unroll below via token rows trow*8+r).
        const char* pfb = (const char*)h + ((size_t)(g * 32 + trow * 8)) * (D_DIM * 4);

        unsigned long long acc[8][8];
        #pragma unroll
        for (int r = 0; r < 8; ++r)
            #pragma unroll
            for (int e = 0; e < 8; ++e) acc[r][e] = 0ull;

        // Warmup: L2 PF for iters 1..5; stage iters 0,1 into slots 0,1.
        #pragma unroll
        for (int p = 1; p < 6; ++p)
            #pragma unroll
            for (int r = 0; r < 8; ++r)
                pf_l2(pfb + (size_t)r * (D_DIM * 4) + p * 128 + (sub & 3) * 32);
        #pragma unroll
        for (int st = 0; st < 2; ++st) {
            const unsigned dst = hbuf0 + st * HBUF_SZ + (unsigned)lane * 16;
            #pragma unroll
            for (int q = 0; q < 8; ++q)
                cp16(dst + q * 512, gst + (size_t)q * 4 * (D_DIM * 4) + st * 128);
            cp_commit();
        }

        int rs = 0;        // read slot  (i % 3)
        int ws = 2;        // write slot ((i+2) % 3)
        #pragma unroll 2
        for (int i = 0; i < NITER; ++i) {
            cp_wait1();                        // stage i complete

            // Read this iter's 32 h values (8 tokens x 4 floats) from smem.
            const char* rb = hbuf0p + rs * HBUF_SZ;
            float4 cc4[8];
            #pragma unroll
            for (int r = 0; r < 8; ++r)
                cc4[r] = *(const float4*)(rb + rdbase + r * 128);

            // Stage iter i+2 into slot ws (reads for that slot finished i-1).
            if (i + 2 < NITER) {
                const unsigned dst = hbuf0 + ws * HBUF_SZ + (unsigned)lane * 16;
                const char* gsi = gst + (size_t)(i + 2) * 128;
                #pragma unroll
                for (int q = 0; q < 8; ++q)
                    cp16(dst + q * 512, gsi + (size_t)q * 4 * (D_DIM * 4));
            }
            cp_commit();

            // L2 PF 6 iters ahead (clamped), one 32B sector per lane-quad.
            const int ipf = (i + 6 < NITER) ? (i + 6) : (NITER - 1);
            #pragma unroll
            for (int r = 0; r < 8; ++r)
                pf_l2(pfb + (size_t)r * (D_DIM * 4) + ipf * 128 + (sub & 3) * 32);

            const float cc[8][4] = {
                {cc4[0].x, cc4[0].y, cc4[0].z, cc4[0].w},
                {cc4[1].x, cc4[1].y, cc4[1].z, cc4[1].w},
                {cc4[2].x, cc4[2].y, cc4[2].z, cc4[2].w},
                {cc4[3].x, cc4[3].y, cc4[3].z, cc4[3].w},
                {cc4[4].x, cc4[4].y, cc4[4].z, cc4[4].w},
                {cc4[5].x, cc4[5].y, cc4[5].z, cc4[5].w},
                {cc4[6].x, cc4[6].y, cc4[6].z, cc4[6].w},
                {cc4[7].x, cc4[7].y, cc4[7].z, cc4[7].w}
            };

            const int kbase = i * 32 + sub * 4;
            #pragma unroll
            for (int j = 0; j < 4; ++j) {
                const unsigned base = ((unsigned)(kbase + j) * 64u) ^ subx;
                ulonglong2 w01 = *(const ulonglong2*)(swb + (base ^ 0u));
                ulonglong2 w23 = *(const ulonglong2*)(swb + (base ^ 16u));
                ulonglong2 n01 = *(const ulonglong2*)(swb + (base ^ 32u));
                ulonglong2 n23 = *(const ulonglong2*)(swb + (base ^ 48u));
                #pragma unroll
                for (int r = 0; r < 8; ++r) {
                    unsigned long long hh = dup2(cc[r][j]);
                    fma2(acc[r][0], w01.x, hh); fma2(acc[r][1], w01.y, hh);
                    fma2(acc[r][2], w23.x, hh); fma2(acc[r][3], w23.y, hh);
                    fma2(acc[r][4], n01.x, hh); fma2(acc[r][5], n01.y, hh);
                    fma2(acc[r][6], n23.x, hh); fma2(acc[r][7], n23.y, hh);
                }
            }

            rs = (rs == 2) ? 0 : rs + 1;
            ws = (ws == 2) ? 0 : ws + 1;
        }

        // Butterfly all-reduce across the 8 sub lanes (xor 1, 2, 4).
        #pragma unroll
        for (int s = 1; s <= 4; s <<= 1) {
            #pragma unroll
            for (int r = 0; r < 8; ++r)
                #pragma unroll
                for (int e = 0; e < 8; ++e) {
                    unsigned long long o = __shfl_xor_sync(0xffffffffu, acc[r][e], s);
                    acc[r][e] = add2(acc[r][e], o);
                }
        }

        // Every lane finishes exactly one token: r = sub (0..7).
        {
            unsigned long long sel[8];
            #pragma unroll
            for (int r = 0; r < 8; ++r)
                if (sub == r) {
                    #pragma unroll
                    for (int e = 0; e < 8; ++e) sel[e] = acc[r][e];
                }

            const int tok = g * 32 + trow * 8 + sub;

            float lg[8], nr[8];
            unpack2(sel[0], lg[0], lg[1]); unpack2(sel[1], lg[2], lg[3]);
            unpack2(sel[2], lg[4], lg[5]); unpack2(sel[3], lg[6], lg[7]);
            unpack2(sel[4], nr[0], nr[1]); unpack2(sel[5], nr[2], nr[3]);
            unpack2(sel[6], nr[4], nr[5]); unpack2(sel[7], nr[6], nr[7]);

            float4 e0 = __ldg((const float4*)(eps + (size_t)tok * 8));
            float4 e1 = __ldg((const float4*)(eps + (size_t)tok * 8) + 1);
            float ee[8] = {e0.x, e0.y, e0.z, e0.w, e1.x, e1.y, e1.z, e1.w};

            float noisy[8];
            #pragma unroll
            for (int e = 0; e < 8; ++e) {
                float x  = nr[e] + bn[e];
                float sp = (x > 0.f) ? (x + log1pf(expf(-x))) : log1pf(expf(x));
                noisy[e] = lg[e] + bw[e] + ee[e] * sp;
            }

            // Full softmax (max-subtracted, matches jax.nn.softmax)
            float m = noisy[0];
            #pragma unroll
            for (int e = 1; e < 8; ++e) m = fmaxf(m, noisy[e]);
            float ex[8], ssum = 0.f;
            #pragma unroll
            for (int e = 0; e < 8; ++e) { ex[e] = expf(noisy[e] - m); ssum += ex[e]; }
            float inv = 1.f / ssum;

            // Top-2, first-occurrence tie-break (matches jax.lax.top_k)
            int i1 = 0; float v1 = noisy[0];
            #pragma unroll
            for (int e = 1; e < 8; ++e) if (noisy[e] > v1) { v1 = noisy[e]; i1 = e; }
            int i2 = -1; float v2 = -3.4e38f;
            #pragma unroll
            for (int e = 0; e < 8; ++e) if (e != i1 && noisy[e] > v2) { v2 = noisy[e]; i2 = e; }

            // Sparse softmax over exactly the two kept entries (others exactly 0)
            float edd = expf(v2 - v1);
            float s1  = 1.f / (1.f + edd);
            float s2  = edd * s1;

            float sp8[8];
            #pragma unroll
            for (int e = 0; e < 8; ++e)
                sp8[e] = (e == i1) ? s1 : ((e == i2) ? s2 : 0.f);

            float* outS = out + (size_t)tok * 8;
            float* outI = out + (size_t)T_TOK * 8  + (size_t)tok * 2;
            float* outF = out + (size_t)T_TOK * 10 + (size_t)tok * 8;

            ((float4*)outS)[0] = make_float4(sp8[0], sp8[1], sp8[2], sp8[3]);
            ((float4*)outS)[1] = make_float4(sp8[4], sp8[5], sp8[6], sp8[7]);
            ((float2*)outI)[0] = make_float2((float)i1, (float)i2);
            ((float4*)outF)[0] = make_float4(ex[0] * inv, ex[1] * inv, ex[2] * inv, ex[3] * inv);
            ((float4*)outF)[1] = make_float4(ex[4] * inv, ex[5] * inv, ex[6] * inv, ex[7] * inv);
        }
    }
}

extern "C" void kernel_launch(void* const* d_in, const int* in_sizes, int n_in,
                              void* d_out, int out_size)
{
    const float* h   = (const float*)d_in[0];
    const float* Ww  = (const float*)d_in[1];
    const float* bw  = (const float*)d_in[2];
    const float* Wn  = (const float*)d_in[3];
    const float* bn  = (const float*)d_in[4];
    const float* eps = (const float*)d_in[5];

    const int smem = SMEM_W + 8 * 3 * HBUF_SZ;   // 131072 + 98304 = 229376
    cudaFuncSetAttribute(router_kernel, cudaFuncAttributeMaxDynamicSharedMemorySize, smem);

    // 128 CTAs x 8 warps = 1024 warp slots = NGROUPS exactly:
    // every SM that gets a CTA runs 8 fully-active warps (2.0/SMSP).
    router_kernel<<<NCTA, 256, smem>>>(h, Ww, bw, Wn, bn, eps, (float*)d_out);
}

// round 13
// speedup vs baseline: 1.0999x; 1.0337x over previous
#include <cuda_runtime.h>

#define T_TOK   32768
#define D_DIM   2048
#define NE      8
#define NGROUPS (T_TOK / 32)   // 1024 groups of 32 tokens
#define NITER   (D_DIM / 32)   // 64 inner iterations
#define NCTA    128            // 128 CTAs x 8 warps = 1024 slots = NGROUPS exactly
#define SMEM_W  131072         // weights region
#define HBUF_SZ 4096           // one h stage buffer (32 tokens x 128B)

// ---- Blackwell packed f32x2 helpers ----
__device__ __forceinline__ unsigned long long dup2(float x) {
    unsigned long long r;
    asm("mov.b64 %0, {%1, %1};" : "=l"(r) : "f"(x));
    return r;
}
__device__ __forceinline__ void fma2(unsigned long long& a, unsigned long long b, unsigned long long c) {
    asm("fma.rn.f32x2 %0, %1, %2, %0;" : "+l"(a) : "l"(b), "l"(c));
}
__device__ __forceinline__ unsigned long long add2(unsigned long long a, unsigned long long b) {
    unsigned long long r;
    asm("add.rn.f32x2 %0, %1, %2;" : "=l"(r) : "l"(a), "l"(b));
    return r;
}
__device__ __forceinline__ void unpack2(unsigned long long v, float& lo, float& hi) {
    asm("mov.b64 {%0, %1}, %2;" : "=f"(lo), "=f"(hi) : "l"(v));
}
__device__ __forceinline__ void cp16(unsigned smem_dst, const void* gsrc) {
    asm volatile("cp.async.cg.shared.global [%0], [%1], 16;" :: "r"(smem_dst), "l"(gsrc));
}
__device__ __forceinline__ void cp_commit() {
    asm volatile("cp.async.commit_group;" ::: "memory");
}
__device__ __forceinline__ void cp_wait1() {
    asm volatile("cp.async.wait_group 1;" ::: "memory");
}

// Persistent kernel: grid=128 CTAs (8 warps each -> 1024 warp slots, exactly
// one 32-token group per warp, 8 active warps on EVERY SM = 2.0/SMSP).
// smem: [0,128K) XOR-swizzled weights ([k][Ww e0..7|Wn e0..7], ^((k>>2)&7)<<4);
//       [128K,224K) per-warp h stage buffers (3 x 4KB each, cp.async.cg).
// Lane = (trow = lane>>3: token octet 0..3, sub = lane&7: k-slice).
// Each lane accumulates 8 tokens; h flows gmem->L2->smem via cp.async with
// stage-ahead 2 (~1900 cyc of latency cover -- no L2 prefetch needed).
extern "C" __global__ void __launch_bounds__(256, 1)
router_kernel(const float* __restrict__ h,  const float* __restrict__ Ww,
              const float* __restrict__ bw, const float* __restrict__ Wn,
              const float* __restrict__ bn, const float* __restrict__ eps,
              float* __restrict__ out)
{
    extern __shared__ char smem_all[];
    char* swb = smem_all;                       // weights

    const int tid = threadIdx.x;

    // Fill weights into smem with swizzle.
    #pragma unroll
    for (int it = 0; it < (D_DIM * NE) / 256; ++it) {
        int idx = tid + it * 256;          // 0..16383
        int k = idx >> 3, e = idx & 7;
        unsigned sx = ((unsigned)(k >> 2) & 7u) << 4;
        unsigned offW = ((unsigned)k * 64u + (unsigned)e * 4u) ^ sx;
        unsigned offN = ((unsigned)k * 64u + 32u + (unsigned)e * 4u) ^ sx;
        *(float*)(swb + offW) = Ww[idx];
        *(float*)(swb + offN) = Wn[idx];
    }
    __syncthreads();

    const int warp = tid >> 5;
    const int lane = tid & 31;
    const int trow = lane >> 3;          // token octet 0..3
    const int sub  = lane & 7;           // k-slice 0..7
    const unsigned subx = (unsigned)sub << 4;   // weight swizzle term

    // This warp's 3 h stage buffers (shared-space u32 addresses).
    const unsigned smem_base_u32 =
        (unsigned)__cvta_generic_to_shared(smem_all);
    const unsigned hbuf0 = smem_base_u32 + SMEM_W + (unsigned)warp * (3 * HBUF_SZ);
    char* hbuf0p = smem_all + SMEM_W + warp * (3 * HBUF_SZ);

    for (int g = warp * gridDim.x + blockIdx.x; g < NGROUPS; g += gridDim.x * 8) {
        // Staging lane role: instr q copies chunk sub (16B) of token q*4+trow.
        const char* gst = (const char*)h
                        + ((size_t)(g * 32 + trow)) * (D_DIM * 4) + sub * 16;
        // Read role: lane reads chunk sub of tokens trow*8 + r.
        const unsigned rdbase = (unsigned)(trow * 1024 + sub * 16);

        unsigned long long acc[8][8];
        #pragma unroll
        for (int r = 0; r < 8; ++r)
            #pragma unroll
            for (int e = 0; e < 8; ++e) acc[r][e] = 0ull;

        // Warmup: stage iters 0,1 into slots 0,1.
        #pragma unroll
        for (int st = 0; st < 2; ++st) {
            const unsigned dst = hbuf0 + st * HBUF_SZ + (unsigned)lane * 16;
            #pragma unroll
            for (int q = 0; q < 8; ++q)
                cp16(dst + q * 512, gst + (size_t)q * 4 * (D_DIM * 4) + st * 128);
            cp_commit();
        }

        int rs = 0;        // read slot  (i % 3)
        int ws = 2;        // write slot ((i+2) % 3)
        #pragma unroll 2
        for (int i = 0; i < NITER; ++i) {
            cp_wait1();                        // stage i complete

            // Read this iter's 32 h values (8 tokens x 4 floats) from smem.
            const char* rb = hbuf0p + rs * HBUF_SZ;
            float4 cc4[8];
            #pragma unroll
            for (int r = 0; r < 8; ++r)
                cc4[r] = *(const float4*)(rb + rdbase + r * 128);

            // Stage iter i+2 into slot ws (reads for that slot finished i-1).
            if (i + 2 < NITER) {
                const unsigned dst = hbuf0 + ws * HBUF_SZ + (unsigned)lane * 16;
                const char* gsi = gst + (size_t)(i + 2) * 128;
                #pragma unroll
                for (int q = 0; q < 8; ++q)
                    cp16(dst + q * 512, gsi + (size_t)q * 4 * (D_DIM * 4));
            }
            cp_commit();

            const float cc[8][4] = {
                {cc4[0].x, cc4[0].y, cc4[0].z, cc4[0].w},
                {cc4[1].x, cc4[1].y, cc4[1].z, cc4[1].w},
                {cc4[2].x, cc4[2].y, cc4[2].z, cc4[2].w},
                {cc4[3].x, cc4[3].y, cc4[3].z, cc4[3].w},
                {cc4[4].x, cc4[4].y, cc4[4].z, cc4[4].w},
                {cc4[5].x, cc4[5].y, cc4[5].z, cc4[5].w},
                {cc4[6].x, cc4[6].y, cc4[6].z, cc4[6].w},
                {cc4[7].x, cc4[7].y, cc4[7].z, cc4[7].w}
            };

            const int kbase = i * 32 + sub * 4;
            #pragma unroll
            for (int j = 0; j < 4; ++j) {
                const unsigned base = ((unsigned)(kbase + j) * 64u) ^ subx;
                ulonglong2 w01 = *(const ulonglong2*)(swb + (base ^ 0u));
                ulonglong2 w23 = *(const ulonglong2*)(swb + (base ^ 16u));
                ulonglong2 n01 = *(const ulonglong2*)(swb + (base ^ 32u));
                ulonglong2 n23 = *(const ulonglong2*)(swb + (base ^ 48u));
                #pragma unroll
                for (int r = 0; r < 8; ++r) {
                    unsigned long long hh = dup2(cc[r][j]);
                    fma2(acc[r][0], w01.x, hh); fma2(acc[r][1], w01.y, hh);
                    fma2(acc[r][2], w23.x, hh); fma2(acc[r][3], w23.y, hh);
                    fma2(acc[r][4], n01.x, hh); fma2(acc[r][5], n01.y, hh);
                    fma2(acc[r][6], n23.x, hh); fma2(acc[r][7], n23.y, hh);
                }
            }

            rs = (rs == 2) ? 0 : rs + 1;
            ws = (ws == 2) ? 0 : ws + 1;
        }

        // Butterfly all-reduce across the 8 sub lanes (xor 1, 2, 4).
        #pragma unroll
        for (int s = 1; s <= 4; s <<= 1) {
            #pragma unroll
            for (int r = 0; r < 8; ++r)
                #pragma unroll
                for (int e = 0; e < 8; ++e) {
                    unsigned long long o = __shfl_xor_sync(0xffffffffu, acc[r][e], s);
                    acc[r][e] = add2(acc[r][e], o);
                }
        }

        // Every lane finishes exactly one token: r = sub (0..7).
        {
            unsigned long long sel[8];
            #pragma unroll
            for (int r = 0; r < 8; ++r)
                if (sub == r) {
                    #pragma unroll
                    for (int e = 0; e < 8; ++e) sel[e] = acc[r][e];
                }

            const int tok = g * 32 + trow * 8 + sub;

            float lg[8], nr[8];
            unpack2(sel[0], lg[0], lg[1]); unpack2(sel[1], lg[2], lg[3]);
            unpack2(sel[2], lg[4], lg[5]); unpack2(sel[3], lg[6], lg[7]);
            unpack2(sel[4], nr[0], nr[1]); unpack2(sel[5], nr[2], nr[3]);
            unpack2(sel[6], nr[4], nr[5]); unpack2(sel[7], nr[6], nr[7]);

            float4 e0 = __ldg((const float4*)(eps + (size_t)tok * 8));
            float4 e1 = __ldg((const float4*)(eps + (size_t)tok * 8) + 1);
            float ee[8] = {e0.x, e0.y, e0.z, e0.w, e1.x, e1.y, e1.z, e1.w};

            float noisy[8];
            #pragma unroll
            for (int e = 0; e < 8; ++e) {
                float x  = nr[e] + bn[e];
                float sp = (x > 0.f) ? (x + log1pf(expf(-x))) : log1pf(expf(x));
                noisy[e] = lg[e] + bw[e] + ee[e] * sp;
            }

            // Full softmax (max-subtracted, matches jax.nn.softmax)
            float m = noisy[0];
            #pragma unroll
            for (int e = 1; e < 8; ++e) m = fmaxf(m, noisy[e]);
            float ex[8], ssum = 0.f;
            #pragma unroll
            for (int e = 0; e < 8; ++e) { ex[e] = expf(noisy[e] - m); ssum += ex[e]; }
            float inv = 1.f / ssum;

            // Top-2, first-occurrence tie-break (matches jax.lax.top_k)
            int i1 = 0; float v1 = noisy[0];
            #pragma unroll
            for (int e = 1; e < 8; ++e) if (noisy[e] > v1) { v1 = noisy[e]; i1 = e; }
            int i2 = -1; float v2 = -3.4e38f;
            #pragma unroll
            for (int e = 0; e < 8; ++e) if (e != i1 && noisy[e] > v2) { v2 = noisy[e]; i2 = e; }

            // Sparse softmax over exactly the two kept entries (others exactly 0)
            float edd = expf(v2 - v1);
            float s1  = 1.f / (1.f + edd);
            float s2  = edd * s1;

            float sp8[8];
            #pragma unroll
            for (int e = 0; e < 8; ++e)
                sp8[e] = (e == i1) ? s1 : ((e == i2) ? s2 : 0.f);

            float* outS = out + (size_t)tok * 8;
            float* outI = out + (size_t)T_TOK * 8  + (size_t)tok * 2;
            float* outF = out + (size_t)T_TOK * 10 + (size_t)tok * 8;

            ((float4*)outS)[0] = make_float4(sp8[0], sp8[1], sp8[2], sp8[3]);
            ((float4*)outS)[1] = make_float4(sp8[4], sp8[5], sp8[6], sp8[7]);
            ((float2*)outI)[0] = make_float2((float)i1, (float)i2);
            ((float4*)outF)[0] = make_float4(ex[0] * inv, ex[1] * inv, ex[2] * inv, ex[3] * inv);
            ((float4*)outF)[1] = make_float4(ex[4] * inv, ex[5] * inv, ex[6] * inv, ex[7] * inv);
        }
    }
}

extern "C" void kernel_launch(void* const* d_in, const int* in_sizes, int n_in,
                              void* d_out, int out_size)
{
    const float* h   = (const float*)d_in[0];
    const float* Ww  = (const float*)d_in[1];
    const float* bw  = (const float*)d_in[2];
    const float* Wn  = (const float*)d_in[3];
    const float* bn  = (const float*)d_in[4];
    const float* eps = (const float*)d_in[5];

    const int smem = SMEM_W + 8 * 3 * HBUF_SZ;   // 131072 + 98304 = 229376
    cudaFuncSetAttribute(router_kernel, cudaFuncAttributeMaxDynamicSharedMemorySize, smem);

    // 128 CTAs x 8 warps = 1024 warp slots = NGROUPS exactly:
    // every SM that gets a CTA runs 8 fully-active warps (2.0/SMSP).
    router_kernel<<<NCTA, 256, smem>>>(h, Ww, bw, Wn, bn, eps, (float*)d_out);
}